// round 8
// baseline (speedup 1.0000x reference)
#include <cuda_runtime.h>

// Gray-Scott residual, 2(y) x 4(x) outputs/thread.
// All 20 main LDG.128 (u+v, spatial+time rows) front-batched for MLP~20,
// warp-shuffle halo expansion afterwards. 5 CTAs/SM, few-warps/fat-MLP regime.
// input (20,8,3,256,256) f32 -> outputs f_u, f_v each (20,8,1,252,252) concatenated.

#define T_DIM 20
#define B_DIM 8
#define HH 256
#define WW 256
#define OH 252
#define OW 252
#define CS (HH * WW)              // 65536
#define TS_ (B_DIM * 3 * CS)      // 1572864
#define OPLANE (OH * OW)          // 63504
#define NOUT (T_DIM * B_DIM * OPLANE)

#define C1f (4.0f / 3.0f)
#define C2f (-1.0f / 12.0f)
#define INV_DX2 40.96f

// Expand an already-loaded aligned float4 into 8 columns via shfl (edge lanes load the
// neighbor float4 directly).
__device__ __forceinline__ void exp8(float4 a, const float* __restrict__ pext, bool edge, float c[8])
{
    c[0] = a.x; c[1] = a.y; c[2] = a.z; c[3] = a.w;
    float b0 = __shfl_down_sync(0xffffffffu, a.x, 1);
    float b1 = __shfl_down_sync(0xffffffffu, a.y, 1);
    float b2 = __shfl_down_sync(0xffffffffu, a.z, 1);
    float b3 = __shfl_down_sync(0xffffffffu, a.w, 1);
    if (edge) {
        const float4 e = *reinterpret_cast<const float4*>(pext);
        b0 = e.x; b1 = e.y; b2 = e.z; b3 = e.w;
    }
    c[4] = b0; c[5] = b1; c[6] = b2; c[7] = b3;
}

// Expand an already-loaded aligned float4 into the center-4 columns (cols +2..+5).
__device__ __forceinline__ void exp4(float4 a, const float* __restrict__ pext, bool edge, float c[4])
{
    float b0 = __shfl_down_sync(0xffffffffu, a.x, 1);
    float b1 = __shfl_down_sync(0xffffffffu, a.y, 1);
    if (edge) {
        const float2 e = *reinterpret_cast<const float2*>(pext);
        b0 = e.x; b1 = e.y;
    }
    c[0] = a.z; c[1] = a.w; c[2] = b0; c[3] = b1;
}

__global__ __launch_bounds__(128, 5) void grayscott_loss_kernel(
    const float* __restrict__ in, float* __restrict__ out)
{
    const int tx   = threadIdx.x;                    // 0..63
    const int ty   = threadIdx.y;                    // 0..1
    const int lane = tx & 31;
    const bool edge = (lane == 31) || (tx == 62);
    const int col0 = min(4 * tx, 248);               // tx==63 duplicates tx==62 (benign)
    const int yy0  = blockIdx.x * 4 + ty * 2;        // output rows yy0, yy0+1
    const int tb   = blockIdx.y;                     // 0..159
    const int t    = tb >> 3;

    const float* __restrict__ ub = in + (size_t)tb * 3 * CS + CS;  // channel 1
    const float* __restrict__ vb = ub + CS;                        // channel 2

    // time derivative scheme: td = al*center + be*x[offA] + ga*x[offB]
    int offA, offB;
    float al, be, ga;
    if (t == 0)              { offA =  TS_;  offB =  2 * TS_; al = -30.0f; be =  40.0f; ga = -10.0f; }
    else if (t == T_DIM - 1) { offA = -TS_;  offB = -2 * TS_; al =  30.0f; be = -40.0f; ga =  10.0f; }
    else                     { offA =  TS_;  offB = -TS_;     al =   0.0f; be =  10.0f; ga = -10.0f; }

    const float* pu = ub + yy0 * WW + col0;
    const float* pv = vb + yy0 * WW + col0;

    // ---------------- front-batched loads: 20 independent LDG.128 ----------------
    const float4 u_r2 = *reinterpret_cast<const float4*>(pu + 2 * WW);
    const float4 u_r3 = *reinterpret_cast<const float4*>(pu + 3 * WW);
    const float4 u_r0 = *reinterpret_cast<const float4*>(pu);
    const float4 u_r1 = *reinterpret_cast<const float4*>(pu + 1 * WW);
    const float4 u_r4 = *reinterpret_cast<const float4*>(pu + 4 * WW);
    const float4 u_r5 = *reinterpret_cast<const float4*>(pu + 5 * WW);
    const float4 u_A0 = *reinterpret_cast<const float4*>(pu + offA + 2 * WW);
    const float4 u_B0 = *reinterpret_cast<const float4*>(pu + offB + 2 * WW);
    const float4 u_A1 = *reinterpret_cast<const float4*>(pu + offA + 3 * WW);
    const float4 u_B1 = *reinterpret_cast<const float4*>(pu + offB + 3 * WW);

    const float4 v_r2 = *reinterpret_cast<const float4*>(pv + 2 * WW);
    const float4 v_r3 = *reinterpret_cast<const float4*>(pv + 3 * WW);
    const float4 v_r0 = *reinterpret_cast<const float4*>(pv);
    const float4 v_r1 = *reinterpret_cast<const float4*>(pv + 1 * WW);
    const float4 v_r4 = *reinterpret_cast<const float4*>(pv + 4 * WW);
    const float4 v_r5 = *reinterpret_cast<const float4*>(pv + 5 * WW);
    const float4 v_A0 = *reinterpret_cast<const float4*>(pv + offA + 2 * WW);
    const float4 v_B0 = *reinterpret_cast<const float4*>(pv + offB + 2 * WW);
    const float4 v_A1 = *reinterpret_cast<const float4*>(pv + offA + 3 * WW);
    const float4 v_B1 = *reinterpret_cast<const float4*>(pv + offB + 3 * WW);

    const float Du = 0.16f, Dv = 0.08f, Ff = 0.06f, FpK = 0.122f;

    // ---------------- u channel: expand + fold into partials ----------------
    float pu0[4], pu1[4], uc0[4], uc1[4];
    {
        float r2[8], r3[8], r0c[4], r1c[4], r4c[4], r5c[4];
        exp8(u_r2, pu + 2 * WW + 4, edge, r2);
        exp8(u_r3, pu + 3 * WW + 4, edge, r3);
        exp4(u_r0, pu + 4,          edge, r0c);
        exp4(u_r1, pu + 1 * WW + 4, edge, r1c);
        exp4(u_r4, pu + 4 * WW + 4, edge, r4c);
        exp4(u_r5, pu + 5 * WW + 4, edge, r5c);
        float A0[4], B0[4], A1[4], B1[4];
        exp4(u_A0, pu + offA + 2 * WW + 4, edge, A0);
        exp4(u_B0, pu + offB + 2 * WW + 4, edge, B0);
        exp4(u_A1, pu + offA + 3 * WW + 4, edge, A1);
        exp4(u_B1, pu + offB + 3 * WW + 4, edge, B1);

        #pragma unroll
        for (int k = 0; k < 4; k++) {
            const float c0 = r2[k + 2];
            const float c1 = r3[k + 2];
            const float lap0 = (C1f * (r2[k + 1] + r2[k + 3] + r1c[k] + r3[k + 2])
                              + C2f * (r2[k] + r2[k + 4] + r0c[k] + r4c[k])
                              - 5.0f * c0) * INV_DX2;
            const float lap1 = (C1f * (r3[k + 1] + r3[k + 3] + r2[k + 2] + r4c[k])
                              + C2f * (r3[k] + r3[k + 4] + r1c[k] + r5c[k])
                              - 5.0f * c1) * INV_DX2;
            const float td0 = al * c0 + be * A0[k] + ga * B0[k];
            const float td1 = al * c1 + be * A1[k] + ga * B1[k];
            pu0[k] = Du * lap0 - td0 + Ff * (1.0f - c0);
            pu1[k] = Du * lap1 - td1 + Ff * (1.0f - c1);
            uc0[k] = c0;
            uc1[k] = c1;
        }
    }

    // ---------------- v channel: expand + finish both outputs ----------------
    float4 fu0, fu1, fv0, fv1;
    {
        float r2[8], r3[8], r0c[4], r1c[4], r4c[4], r5c[4];
        exp8(v_r2, pv + 2 * WW + 4, edge, r2);
        exp8(v_r3, pv + 3 * WW + 4, edge, r3);
        exp4(v_r0, pv + 4,          edge, r0c);
        exp4(v_r1, pv + 1 * WW + 4, edge, r1c);
        exp4(v_r4, pv + 4 * WW + 4, edge, r4c);
        exp4(v_r5, pv + 5 * WW + 4, edge, r5c);
        float A0[4], B0[4], A1[4], B1[4];
        exp4(v_A0, pv + offA + 2 * WW + 4, edge, A0);
        exp4(v_B0, pv + offB + 2 * WW + 4, edge, B0);
        exp4(v_A1, pv + offA + 3 * WW + 4, edge, A1);
        exp4(v_B1, pv + offB + 3 * WW + 4, edge, B1);

        float* pfu0 = &fu0.x; float* pfu1 = &fu1.x;
        float* pfv0 = &fv0.x; float* pfv1 = &fv1.x;
        #pragma unroll
        for (int k = 0; k < 4; k++) {
            const float c0 = r2[k + 2];
            const float c1 = r3[k + 2];
            const float lap0 = (C1f * (r2[k + 1] + r2[k + 3] + r1c[k] + r3[k + 2])
                              + C2f * (r2[k] + r2[k + 4] + r0c[k] + r4c[k])
                              - 5.0f * c0) * INV_DX2;
            const float lap1 = (C1f * (r3[k + 1] + r3[k + 3] + r2[k + 2] + r4c[k])
                              + C2f * (r3[k] + r3[k + 4] + r1c[k] + r5c[k])
                              - 5.0f * c1) * INV_DX2;
            const float td0 = al * c0 + be * A0[k] + ga * B0[k];
            const float td1 = al * c1 + be * A1[k] + ga * B1[k];
            const float uvv0 = uc0[k] * c0 * c0;
            const float uvv1 = uc1[k] * c1 * c1;
            pfu0[k] = pu0[k] - uvv0;
            pfu1[k] = pu1[k] - uvv1;
            pfv0[k] = Dv * lap0 + uvv0 - FpK * c0 - td0;
            pfv1[k] = Dv * lap1 + uvv1 - FpK * c1 - td1;
        }
    }

    const size_t o = (size_t)tb * OPLANE + (size_t)yy0 * OW + col0;
    *reinterpret_cast<float4*>(out + o)              = fu0;
    *reinterpret_cast<float4*>(out + o + OW)         = fu1;
    *reinterpret_cast<float4*>(out + o + NOUT)       = fv0;
    *reinterpret_cast<float4*>(out + o + NOUT + OW)  = fv1;
}

extern "C" void kernel_launch(void* const* d_in, const int* in_sizes, int n_in,
                              void* d_out, int out_size)
{
    const float* in = (const float*)d_in[0];
    float* out = (float*)d_out;
    dim3 block(64, 2, 1);                  // 128 threads, 4 full warps
    dim3 grid(OH / 4, T_DIM * B_DIM, 1);   // 63 x 160
    grayscott_loss_kernel<<<grid, block>>>(in, out);
}

// round 9
// speedup vs baseline: 1.5567x; 1.5567x over previous
#include <cuda_runtime.h>

// Gray-Scott residual, 2(y) x 4(x) outputs/thread, ZERO shuffles:
// center rows = 2 aligned LDG.128 (8 cols), narrow/time rows = 2 aligned LDG.64 (exact 4 cols).
// Channel-phased. input (20,8,3,256,256) f32 -> f_u, f_v each (20,8,1,252,252) concatenated.

#define T_DIM 20
#define B_DIM 8
#define HH 256
#define WW 256
#define OH 252
#define OW 252
#define CS (HH * WW)              // 65536
#define TS_ (B_DIM * 3 * CS)      // 1572864
#define OPLANE (OH * OW)          // 63504
#define NOUT (T_DIM * B_DIM * OPLANE)

#define C1f (4.0f / 3.0f)
#define C2f (-1.0f / 12.0f)
#define INV_DX2 40.96f

// Narrow row: exactly cols col0+2..col0+5 via two aligned LDG.64 (p points at col0 of the row).
__device__ __forceinline__ void ldn(const float* __restrict__ p, float n[4])
{
    const float2 a = *reinterpret_cast<const float2*>(p + 2);
    const float2 b = *reinterpret_cast<const float2*>(p + 4);
    n[0] = a.x; n[1] = a.y; n[2] = b.x; n[3] = b.y;
}

// One channel, one 2x4 tile: laplacian (scaled), centers, time-derivatives.
__device__ __forceinline__ void chan(
    const float* __restrict__ p,      // base + yy0*WW + col0
    int offA, int offB, float al, float be, float ga,
    float lap0[4], float lap1[4], float c0[4], float c1[4],
    float td0[4], float td1[4])
{
    // center rows: input rows +2, +3 — 8 cols each, two aligned LDG.128
    const float4 c2a = *reinterpret_cast<const float4*>(p + 2 * WW);
    const float4 c2b = *reinterpret_cast<const float4*>(p + 2 * WW + 4);
    const float4 c3a = *reinterpret_cast<const float4*>(p + 3 * WW);
    const float4 c3b = *reinterpret_cast<const float4*>(p + 3 * WW + 4);

    // narrow rows: vertical halo + time rows — exact 4 cols via LDG.64 pairs
    float n0[4], n1[4], n4[4], n5[4], A0[4], B0[4], A1[4], B1[4];
    ldn(p,               n0);
    ldn(p + 1 * WW,      n1);
    ldn(p + 4 * WW,      n4);
    ldn(p + 5 * WW,      n5);
    ldn(p + offA + 2 * WW, A0);
    ldn(p + offB + 2 * WW, B0);
    ldn(p + offA + 3 * WW, A1);
    ldn(p + offB + 3 * WW, B1);

    const float c2[8] = { c2a.x, c2a.y, c2a.z, c2a.w, c2b.x, c2b.y, c2b.z, c2b.w };
    const float c3[8] = { c3a.x, c3a.y, c3a.z, c3a.w, c3b.x, c3b.y, c3b.z, c3b.w };

    #pragma unroll
    for (int k = 0; k < 4; k++) {
        const float cc0 = c2[k + 2];
        const float cc1 = c3[k + 2];
        lap0[k] = (C1f * (c2[k + 1] + c2[k + 3] + n1[k] + cc1)
                 + C2f * (c2[k] + c2[k + 4] + n0[k] + n4[k])
                 - 5.0f * cc0) * INV_DX2;
        lap1[k] = (C1f * (c3[k + 1] + c3[k + 3] + cc0 + n4[k])
                 + C2f * (c3[k] + c3[k + 4] + n1[k] + n5[k])
                 - 5.0f * cc1) * INV_DX2;
        c0[k] = cc0;
        c1[k] = cc1;
        td0[k] = al * cc0 + be * A0[k] + ga * B0[k];
        td1[k] = al * cc1 + be * A1[k] + ga * B1[k];
    }
}

__global__ __launch_bounds__(128, 7) void grayscott_loss_kernel(
    const float* __restrict__ in, float* __restrict__ out)
{
    const int tx   = threadIdx.x;                    // 0..63
    const int ty   = threadIdx.y;                    // 0..1
    const int col0 = min(4 * tx, 248);               // tx==63 duplicates tx==62 (benign)
    const int yy0  = blockIdx.x * 4 + ty * 2;        // output rows yy0, yy0+1
    const int tb   = blockIdx.y;                     // 0..159
    const int t    = tb >> 3;

    const float* __restrict__ ub = in + (size_t)tb * 3 * CS + CS;  // channel 1
    const float* __restrict__ vb = ub + CS;                        // channel 2

    // time derivative: td = al*center + be*x[offA] + ga*x[offB]
    int offA, offB;
    float al, be, ga;
    if (t == 0)              { offA =  TS_;  offB =  2 * TS_; al = -30.0f; be =  40.0f; ga = -10.0f; }
    else if (t == T_DIM - 1) { offA = -TS_;  offB = -2 * TS_; al =  30.0f; be = -40.0f; ga =  10.0f; }
    else                     { offA =  TS_;  offB = -TS_;     al =   0.0f; be =  10.0f; ga = -10.0f; }

    const float* pu = ub + yy0 * WW + col0;
    const float* pv = vb + yy0 * WW + col0;

    const float Du = 0.16f, Dv = 0.08f, Ff = 0.06f, FpK = 0.122f;

    // ---- u phase: fold to 16 live partials ----
    float pu0[4], pu1[4], uc0[4], uc1[4];
    {
        float lap0[4], lap1[4], c0[4], c1[4], td0[4], td1[4];
        chan(pu, offA, offB, al, be, ga, lap0, lap1, c0, c1, td0, td1);
        #pragma unroll
        for (int k = 0; k < 4; k++) {
            pu0[k] = Du * lap0[k] - td0[k] + Ff * (1.0f - c0[k]);
            pu1[k] = Du * lap1[k] - td1[k] + Ff * (1.0f - c1[k]);
            uc0[k] = c0[k];
            uc1[k] = c1[k];
        }
    }

    // ---- v phase: finish both outputs ----
    float4 fu0, fu1, fv0, fv1;
    {
        float lap0[4], lap1[4], c0[4], c1[4], td0[4], td1[4];
        chan(pv, offA, offB, al, be, ga, lap0, lap1, c0, c1, td0, td1);
        float* pfu0 = &fu0.x; float* pfu1 = &fu1.x;
        float* pfv0 = &fv0.x; float* pfv1 = &fv1.x;
        #pragma unroll
        for (int k = 0; k < 4; k++) {
            const float uvv0 = uc0[k] * c0[k] * c0[k];
            const float uvv1 = uc1[k] * c1[k] * c1[k];
            pfu0[k] = pu0[k] - uvv0;
            pfu1[k] = pu1[k] - uvv1;
            pfv0[k] = Dv * lap0[k] + uvv0 - FpK * c0[k] - td0[k];
            pfv1[k] = Dv * lap1[k] + uvv1 - FpK * c1[k] - td1[k];
        }
    }

    const size_t o = (size_t)tb * OPLANE + (size_t)yy0 * OW + col0;
    *reinterpret_cast<float4*>(out + o)              = fu0;
    *reinterpret_cast<float4*>(out + o + OW)         = fu1;
    *reinterpret_cast<float4*>(out + o + NOUT)       = fv0;
    *reinterpret_cast<float4*>(out + o + NOUT + OW)  = fv1;
}

extern "C" void kernel_launch(void* const* d_in, const int* in_sizes, int n_in,
                              void* d_out, int out_size)
{
    const float* in = (const float*)d_in[0];
    float* out = (float*)d_out;
    dim3 block(64, 2, 1);                  // 128 threads, 4 warps
    dim3 grid(OH / 4, T_DIM * B_DIM, 1);   // 63 x 160
    grayscott_loss_kernel<<<grid, block>>>(in, out);
}